// round 15
// baseline (speedup 1.0000x reference)
#include <cuda_runtime.h>
#include <cstdint>

#define PS 5
#define NT 2
#define PH 536
#define PW 536
#define OH 532
#define OW 532
#define PDIM 75
#define HW (PH*PW)

#define TX 45
#define TXH 49               // patch window width
#define CHUNK (TXH*PDIM)     // 3675 floats per window row
#define CSTRIDE 3680         // slot stride (14720 B, 16B-aligned, room for moff)
#define WSTR 56              // weight slot stride (224 B)
#define RING 15              // row-ring slots
#define RPS 5                // output rows per stage
#define NB 4                 // stage mbarriers
#define TPB 256
#define NX 12                // 12*45 = 540 >= 532
#define NSTRIPS 6
#define SROWS 89             // 6*89 = 534 >= 532

// smem layout (floats)
#define SVAL_OFF   0
#define SWT_OFF    (RING*CSTRIDE)             // 55200
#define SMEANS_OFF (SWT_OFF + RING*WSTR)      // 56040
#define MBAR_OFF   (SMEANS_OFF + 8)           // 56048 (byte 224192, 8B aligned)
#define SMEM_FLOATS (MBAR_OFF + 2*NB)
#define SMEM_BYTES  (SMEM_FLOATS*4)           // 224,256 B

#define MEANS_CHUNKS 24      // 6*24 = 144 blocks, one clean wave

__device__ float g_part[6 * MEANS_CHUNKS];

// ---------------- PTX helpers ------------------------------------------------
__device__ __forceinline__ uint32_t smem_u32(const void* p) {
    return (uint32_t)__cvta_generic_to_shared(p);
}
__device__ __forceinline__ void mbar_init(uint32_t a, uint32_t cnt) {
    asm volatile("mbarrier.init.shared.b64 [%0], %1;" :: "r"(a), "r"(cnt) : "memory");
}
__device__ __forceinline__ void mbar_expect(uint32_t a, uint32_t bytes) {
    asm volatile("mbarrier.arrive.expect_tx.shared.b64 _, [%0], %1;"
                 :: "r"(a), "r"(bytes) : "memory");
}
__device__ __forceinline__ void mbar_wait(uint32_t a, uint32_t parity) {
    asm volatile(
        "{\n\t.reg .pred P;\n\t"
        "WL_%=:\n\t"
        "mbarrier.try_wait.parity.shared.b64 P, [%0], %1, 0x989680;\n\t"
        "@P bra.uni WD_%=;\n\t"
        "bra.uni WL_%=;\n\t"
        "WD_%=:\n\t}"
        :: "r"(a), "r"(parity) : "memory");
}
__device__ __forceinline__ void bulk_g2s(uint32_t dst, const void* src,
                                         uint32_t bytes, uint32_t mbar) {
    asm volatile(
        "cp.async.bulk.shared::cta.global.mbarrier::complete_tx::bytes "
        "[%0], [%1], %2, [%3];"
        :: "r"(dst), "l"(src), "r"(bytes), "r"(mbar) : "memory");
}
__device__ __forceinline__ void grid_dep_wait() {
    asm volatile("griddepcontrol.wait;" ::: "memory");
}

// ---------------- means: partial sums ----------------------------------------
__global__ void __launch_bounds__(512)
means_partial_kernel(const float* __restrict__ noisy) {
    int tc    = blockIdx.x;          // 0..5
    int chunk = blockIdx.y;          // 0..MEANS_CHUNKS-1
    const int plane = OH * OW;
    const float4* p = (const float4*)(noisy + (size_t)tc * plane);
    const int n4 = plane / 4;        // 70756
    float s = 0.f;
    #pragma unroll 8
    for (int i = chunk * 512 + threadIdx.x; i < n4; i += MEANS_CHUNKS * 512) {
        float4 v = __ldg(p + i);
        s += (v.x + v.y) + (v.z + v.w);
    }
    __shared__ float red[32];
    #pragma unroll
    for (int o = 16; o; o >>= 1) s += __shfl_down_sync(0xffffffffu, s, o);
    if ((threadIdx.x & 31) == 0) red[threadIdx.x >> 5] = s;
    __syncthreads();
    if (threadIdx.x < 32) {
        float v = (threadIdx.x < 16) ? red[threadIdx.x] : 0.f;
        #pragma unroll
        for (int o = 16; o; o >>= 1) v += __shfl_down_sync(0xffffffffu, v, o);
        if (threadIdx.x == 0) g_part[tc * MEANS_CHUNKS + chunk] = v;
    }
}

// ---------------- persistent fold kernel --------------------------------------
extern __shared__ float smem[];

__global__ void __launch_bounds__(TPB, 1)
fold_kernel(const float* __restrict__ deno,
            const float* __restrict__ pwts,
            float* __restrict__ out) {
    const int t     = blockIdx.z;
    const int strip = blockIdx.y;
    const int x0    = blockIdx.x * TX;
    const int xbase = min(x0, PW - TXH);   // 45k or 487
    const int xoff  = x0 - xbase;

    const int ys = strip * SROWS;
    const int ye = min(ys + SROWS, OH);
    const int nstages = (ye - ys + RPS - 1) / RPS;   // 18

    const float* dptr = deno + (size_t)t * HW * PDIM;
    const float* wptr = pwts + (size_t)t * HW;

    float* sval   = smem + SVAL_OFF;
    float* swt    = smem + SWT_OFF;
    float* smeans = smem + SMEANS_OFF;
    const uint32_t mb0   = smem_u32(smem + MBAR_OFF);
    const uint32_t svalA = smem_u32(sval);
    const uint32_t swtA  = smem_u32(swt);

    const int tid = threadIdx.x;

    // Align-down offsets: xbase not a multiple of 4 in general.
    // (row base rbase = r*536 + xbase; 536*75 ≡ 0 mod 4, so offsets are
    //  constant per CTA.)  Checked: worst-case reads end exactly at buffer end.
    const int moff = (xbase * 3) & 3;                          // (xbase*75) mod 4
    const int woff = xbase & 3;
    const uint32_t vbytes = (uint32_t)(((moff + CHUNK + 3) >> 2) << 4);  // <=14720
    const uint32_t wbytes = (uint32_t)(((woff + TXH + 3) >> 2) << 4);    // <=224

    if (tid < NB) mbar_init(mb0 + tid * 8, 1);
    __syncthreads();

    // -------- deep prologue: stage 0 rows [ys,ys+9) + stage 1 rows [+9,+14) --
    if (tid == 0) {
        asm volatile("fence.proxy.async.shared::cta;" ::: "memory");
        {
            const int r0 = ys, r1 = min(ys + RPS + 4, ye + 4);
            mbar_expect(mb0, (uint32_t)((r1 - r0) * (vbytes + wbytes)));
            for (int r = r0; r < r1; r++) {
                const int slot  = r % RING;
                const int rbase = r * PW + xbase;
                bulk_g2s(svalA + (uint32_t)(slot * CSTRIDE) * 4,
                         dptr + (size_t)rbase * PDIM - moff, vbytes, mb0);
                bulk_g2s(swtA + (uint32_t)(slot * WSTR) * 4,
                         wptr + rbase - woff, wbytes, mb0);
            }
        }
        if (nstages > 1) {
            const int r0 = ys + RPS + 4, r1 = min(ys + 2 * RPS + 4, ye + 4);
            mbar_expect(mb0 + 8, (uint32_t)((r1 - r0) * (vbytes + wbytes)));
            for (int r = r0; r < r1; r++) {
                const int slot  = r % RING;
                const int rbase = r * PW + xbase;
                bulk_g2s(svalA + (uint32_t)(slot * CSTRIDE) * 4,
                         dptr + (size_t)rbase * PDIM - moff, vbytes, mb0 + 8);
                bulk_g2s(swtA + (uint32_t)(slot * WSTR) * 4,
                         wptr + rbase - woff, wbytes, mb0 + 8);
            }
        }
    }

    // gather thread map: 5 rows x 45 cols = 225 active threads
    const int grow = tid / TX;            // 0..5
    const int gcol = tid - grow * TX;
    const bool gact = (tid < RPS * TX);
    const int Xo  = x0 + gcol;
    const int lxb = xoff + gcol;

    const float* svalc = sval + moff;
    const float* swtc  = swt + woff;

    float m0 = 0.f, m1 = 0.f, m2 = 0.f;
    const size_t plane = (size_t)OH * OW;

    // -------- stage loop: 5 rows/stage; stages 0,1 already in flight ---------
    for (int s = 0; s < nstages; s++) {
        if (tid == 0 && s >= 1 && s + 1 < nstages) {
            const int r0 = ys + RPS * s + RPS + 4;
            const int r1 = min(ys + RPS * (s + 1) + RPS + 4, ye + 4);
            const uint32_t mb = mb0 + ((s + 1) % NB) * 8;
            mbar_expect(mb, (uint32_t)((r1 - r0) * (vbytes + wbytes)));
            for (int r = r0; r < r1; r++) {
                const int slot  = r % RING;
                const int rbase = r * PW + xbase;
                bulk_g2s(svalA + (uint32_t)(slot * CSTRIDE) * 4,
                         dptr + (size_t)rbase * PDIM - moff, vbytes, mb);
                bulk_g2s(swtA + (uint32_t)(slot * WSTR) * 4,
                         wptr + rbase - woff, wbytes, mb);
            }
        }

        mbar_wait(mb0 + (s % NB) * 8, (uint32_t)((s >> 2) & 1));

        const int Yo = ys + RPS * s + grow;
        const bool active = gact && (Yo < ye) && (Xo < OW);

        float a0 = 0.f, a1 = 0.f, a2 = 0.f, cnt = 0.f;
        if (active) {
            #pragma unroll
            for (int i = 0; i < PS; i++) {
                const int row = Yo + 4 - i;
                const int sl  = row % RING;
                const float* vrow = svalc + sl * CSTRIDE;
                const float* wrow = swtc + sl * WSTR;
                #pragma unroll
                for (int j = 0; j < PS; j++) {
                    const int lx = lxb + 4 - j;
                    const float w = wrow[lx];
                    const float* v = vrow + lx * PDIM;  // stride 75
                    const int sidx = i * PS + j;
                    cnt += w;
                    a0 = fmaf(v[sidx],      w, a0);
                    a1 = fmaf(v[25 + sidx], w, a1);
                    a2 = fmaf(v[50 + sidx], w, a2);
                }
            }
        }

        if (s == 0) {
            // Deferred PDL dependency (no-op if serialized); means reduce.
            grid_dep_wait();
            if (tid < 192) {
                const int c = tid >> 5, lane = tid & 31;   // c = 0..5
                float v = (lane < MEANS_CHUNKS) ? g_part[c * MEANS_CHUNKS + lane] : 0.f;
                #pragma unroll
                for (int o = 16; o; o >>= 1) v += __shfl_down_sync(0xffffffffu, v, o);
                if (lane == 0) smeans[c] = v * (1.0f / (float)(OH * OW));
            }
            __syncthreads();
            m0 = smeans[t * 3 + 0];
            m1 = smeans[t * 3 + 1];
            m2 = smeans[t * 3 + 2];
        }

        if (active) {
            const float inv = 0.5f / cnt;
            size_t o = (size_t)t * 3 * plane + (size_t)Yo * OW + Xo;
            out[o]             = a0 * inv + m0;
            out[o + plane]     = a1 * inv + m1;
            out[o + 2 * plane] = a2 * inv + m2;
        }
        __syncthreads();   // stage boundary: protects ring-slot reuse
    }
}

// ---------------- launch ------------------------------------------------------
extern "C" void kernel_launch(void* const* d_in, const int* in_sizes, int n_in,
                              void* d_out, int out_size) {
    const float* noisy = (const float*)d_in[0];
    const float* deno  = (const float*)d_in[1];
    const float* pwts  = (const float*)d_in[2];
    float* out = (float*)d_out;

    cudaFuncSetAttribute(fold_kernel,
                         cudaFuncAttributeMaxDynamicSharedMemorySize,
                         SMEM_BYTES);

    dim3 mg(6, MEANS_CHUNKS);
    means_partial_kernel<<<mg, 512>>>(noisy);

    // PDL as in R13 (fire at drain; dependency deferred in-kernel to s==0).
    cudaLaunchAttribute attrs[1];
    attrs[0].id = cudaLaunchAttributeProgrammaticStreamSerialization;
    attrs[0].val.programmaticStreamSerializationAllowed = 1;

    cudaLaunchConfig_t cfg = {};
    cfg.gridDim  = dim3(NX, NSTRIPS, NT);   // 12 x 6 x 2 = 144 CTAs, one wave
    cfg.blockDim = dim3(TPB, 1, 1);
    cfg.dynamicSmemBytes = SMEM_BYTES;
    cfg.stream = 0;
    cfg.attrs = attrs;
    cfg.numAttrs = 1;

    cudaLaunchKernelEx(&cfg, fold_kernel, deno, pwts, out);
}

// round 16
// speedup vs baseline: 1.0305x; 1.0305x over previous
#include <cuda_runtime.h>
#include <cstdint>

#define PS 5
#define NT 2
#define PH 536
#define PW 536
#define OH 532
#define OW 532
#define PDIM 75
#define HW (PH*PW)

#define TX 30
#define TXH 34               // patch window width
#define CHUNK (TXH*PDIM)     // 2550 floats per window row
#define CSTRIDE 2556         // slot stride (10224 B, 16B-aligned, slack for moff)
#define WSTR 40              // weight slot stride (160 B)
#define RING 20              // row-ring slots
#define RPS 8                // output rows per stage
#define NB 4                 // stage mbarriers
#define TPB 256
#define NX 18                // 18*30 = 540 >= 532
#define NSTRIPS 4
#define SROWS 133            // 4*133 = 532

// smem layout (floats)
#define SVAL_OFF   0
#define SWT_OFF    (RING*CSTRIDE)             // 51120
#define SMEANS_OFF (SWT_OFF + RING*WSTR)      // 51920
#define MBAR_OFF   (SMEANS_OFF + 8)           // 51928 (byte 207712, 16B aligned)
#define SMEM_FLOATS (MBAR_OFF + 2*NB)
#define SMEM_BYTES  (SMEM_FLOATS*4)           // 207,744 B

#define MEANS_CHUNKS 24      // 6*24 = 144 blocks, one clean wave

__device__ float g_part[6 * MEANS_CHUNKS];

// ---------------- PTX helpers ------------------------------------------------
__device__ __forceinline__ uint32_t smem_u32(const void* p) {
    return (uint32_t)__cvta_generic_to_shared(p);
}
__device__ __forceinline__ void mbar_init(uint32_t a, uint32_t cnt) {
    asm volatile("mbarrier.init.shared.b64 [%0], %1;" :: "r"(a), "r"(cnt) : "memory");
}
__device__ __forceinline__ void mbar_expect(uint32_t a, uint32_t bytes) {
    asm volatile("mbarrier.arrive.expect_tx.shared.b64 _, [%0], %1;"
                 :: "r"(a), "r"(bytes) : "memory");
}
__device__ __forceinline__ void mbar_wait(uint32_t a, uint32_t parity) {
    asm volatile(
        "{\n\t.reg .pred P;\n\t"
        "WL_%=:\n\t"
        "mbarrier.try_wait.parity.shared.b64 P, [%0], %1, 0x989680;\n\t"
        "@P bra.uni WD_%=;\n\t"
        "bra.uni WL_%=;\n\t"
        "WD_%=:\n\t}"
        :: "r"(a), "r"(parity) : "memory");
}
__device__ __forceinline__ void bulk_g2s(uint32_t dst, const void* src,
                                         uint32_t bytes, uint32_t mbar) {
    asm volatile(
        "cp.async.bulk.shared::cta.global.mbarrier::complete_tx::bytes "
        "[%0], [%1], %2, [%3];"
        :: "r"(dst), "l"(src), "r"(bytes), "r"(mbar) : "memory");
}
__device__ __forceinline__ void grid_dep_wait() {
    asm volatile("griddepcontrol.wait;" ::: "memory");
}

// ---------------- means: partial sums ----------------------------------------
__global__ void __launch_bounds__(512)
means_partial_kernel(const float* __restrict__ noisy) {
    int tc    = blockIdx.x;          // 0..5
    int chunk = blockIdx.y;          // 0..MEANS_CHUNKS-1
    const int plane = OH * OW;
    const float4* p = (const float4*)(noisy + (size_t)tc * plane);
    const int n4 = plane / 4;        // 70756
    float s = 0.f;
    #pragma unroll 8
    for (int i = chunk * 512 + threadIdx.x; i < n4; i += MEANS_CHUNKS * 512) {
        float4 v = __ldg(p + i);
        s += (v.x + v.y) + (v.z + v.w);
    }
    __shared__ float red[32];
    #pragma unroll
    for (int o = 16; o; o >>= 1) s += __shfl_down_sync(0xffffffffu, s, o);
    if ((threadIdx.x & 31) == 0) red[threadIdx.x >> 5] = s;
    __syncthreads();
    if (threadIdx.x < 32) {
        float v = (threadIdx.x < 16) ? red[threadIdx.x] : 0.f;
        #pragma unroll
        for (int o = 16; o; o >>= 1) v += __shfl_down_sync(0xffffffffu, v, o);
        if (threadIdx.x == 0) g_part[tc * MEANS_CHUNKS + chunk] = v;
    }
}

// ---------------- persistent fold kernel --------------------------------------
extern __shared__ float smem[];

__global__ void __launch_bounds__(TPB, 1)
fold_kernel(const float* __restrict__ deno,
            const float* __restrict__ pwts,
            float* __restrict__ out) {
    const int t     = blockIdx.z;
    const int strip = blockIdx.y;
    const int x0    = blockIdx.x * TX;
    const int xbase = min(x0, PW - TXH);   // 30k or 502
    const int xoff  = x0 - xbase;

    const int ys = strip * SROWS;
    const int ye = min(ys + SROWS, OH);
    const int nstages = (ye - ys + RPS - 1) / RPS;   // 17

    const float* dptr = deno + (size_t)t * HW * PDIM;
    const float* wptr = pwts + (size_t)t * HW;

    float* sval   = smem + SVAL_OFF;
    float* swt    = smem + SWT_OFF;
    float* smeans = smem + SMEANS_OFF;
    const uint32_t mb0   = smem_u32(smem + MBAR_OFF);
    const uint32_t svalA = smem_u32(sval);
    const uint32_t swtA  = smem_u32(swt);

    const int tid = threadIdx.x;
    const int tx  = tid & 31;
    const int wid = tid >> 5;          // output row within stage
    const int Xo  = x0 + tx;

    // Align-down offsets (constant per CTA; verified: worst-case reads end
    // exactly at the slab/array end, no overrun).
    const int moff = (xbase * 3) & 3;                          // (xbase*75) mod 4
    const int woff = xbase & 3;
    const uint32_t vbytes = (uint32_t)(((moff + CHUNK + 3) >> 2) << 4);  // <=10208
    const uint32_t wbytes = (uint32_t)(((woff + TXH + 3) >> 2) << 4);    // <=144

    if (tid < NB) mbar_init(mb0 + tid * 8, 1);
    __syncthreads();

    // -------- deep prologue: stage 0 rows [ys,ys+12) + stage 1 rows [+12,+20)
    if (tid == 0) {
        asm volatile("fence.proxy.async.shared::cta;" ::: "memory");
        {
            const int r0 = ys, r1 = min(ys + RPS + 4, ye + 4);
            mbar_expect(mb0, (uint32_t)((r1 - r0) * (vbytes + wbytes)));
            for (int r = r0; r < r1; r++) {
                const int slot  = r % RING;
                const int rbase = r * PW + xbase;
                bulk_g2s(svalA + (uint32_t)(slot * CSTRIDE) * 4,
                         dptr + (size_t)rbase * PDIM - moff, vbytes, mb0);
                bulk_g2s(swtA + (uint32_t)(slot * WSTR) * 4,
                         wptr + rbase - woff, wbytes, mb0);
            }
        }
        if (nstages > 1) {
            const int r0 = ys + RPS + 4, r1 = min(ys + 2 * RPS + 4, ye + 4);
            mbar_expect(mb0 + 8, (uint32_t)((r1 - r0) * (vbytes + wbytes)));
            for (int r = r0; r < r1; r++) {
                const int slot  = r % RING;
                const int rbase = r * PW + xbase;
                bulk_g2s(svalA + (uint32_t)(slot * CSTRIDE) * 4,
                         dptr + (size_t)rbase * PDIM - moff, vbytes, mb0 + 8);
                bulk_g2s(swtA + (uint32_t)(slot * WSTR) * 4,
                         wptr + rbase - woff, wbytes, mb0 + 8);
            }
        }
    }

    const float* svalc = sval + moff;
    const float* swtc  = swt + woff;

    float m0 = 0.f, m1 = 0.f, m2 = 0.f;
    const size_t plane = (size_t)OH * OW;

    // -------- stage loop: 8 rows/stage; stages 0,1 already in flight ---------
    for (int s = 0; s < nstages; s++) {
        if (tid == 0 && s >= 1 && s + 1 < nstages) {
            const int r0 = ys + RPS * s + RPS + 4;
            const int r1 = min(ys + RPS * (s + 1) + RPS + 4, ye + 4);
            const uint32_t mb = mb0 + ((s + 1) % NB) * 8;
            mbar_expect(mb, (uint32_t)((r1 - r0) * (vbytes + wbytes)));
            for (int r = r0; r < r1; r++) {
                const int slot  = r % RING;
                const int rbase = r * PW + xbase;
                bulk_g2s(svalA + (uint32_t)(slot * CSTRIDE) * 4,
                         dptr + (size_t)rbase * PDIM - moff, vbytes, mb);
                bulk_g2s(swtA + (uint32_t)(slot * WSTR) * 4,
                         wptr + rbase - woff, wbytes, mb);
            }
        }

        mbar_wait(mb0 + (s % NB) * 8, (uint32_t)((s >> 2) & 1));

        const int Yo = ys + RPS * s + wid;
        // tx < TX guard is essential: lanes 30,31 would overread the slot.
        const bool active = (tx < TX) && (Yo < ye) && (Xo < OW);

        float a0 = 0.f, a1 = 0.f, a2 = 0.f, cnt = 0.f;
        if (active) {
            const int sb = (ys + RPS * s) % RING;
            #pragma unroll
            for (int i = 0; i < PS; i++) {
                int sl = sb + wid + 4 - i;
                if (sl >= RING) sl -= RING;
                const float* vrow = svalc + sl * CSTRIDE;
                const float* wrow = swtc + sl * WSTR;
                #pragma unroll
                for (int j = 0; j < PS; j++) {
                    const int lx = xoff + tx + 4 - j;
                    const float w = wrow[lx];
                    const float* v = vrow + lx * PDIM;  // stride 75: conflict-free
                    const int sidx = i * PS + j;
                    cnt += w;
                    a0 = fmaf(v[sidx],      w, a0);
                    a1 = fmaf(v[25 + sidx], w, a1);
                    a2 = fmaf(v[50 + sidx], w, a2);
                }
            }
        }

        if (s == 0) {
            // Deferred PDL dependency (no-op if serialized); means reduce.
            grid_dep_wait();
            if (tid < 192) {
                const int c = tid >> 5, lane = tid & 31;   // c = 0..5
                float v = (lane < MEANS_CHUNKS) ? g_part[c * MEANS_CHUNKS + lane] : 0.f;
                #pragma unroll
                for (int o = 16; o; o >>= 1) v += __shfl_down_sync(0xffffffffu, v, o);
                if (lane == 0) smeans[c] = v * (1.0f / (float)(OH * OW));
            }
            __syncthreads();
            m0 = smeans[t * 3 + 0];
            m1 = smeans[t * 3 + 1];
            m2 = smeans[t * 3 + 2];
        }

        if (active) {
            const float inv = 0.5f / cnt;
            size_t o = (size_t)t * 3 * plane + (size_t)Yo * OW + Xo;
            out[o]             = a0 * inv + m0;
            out[o + plane]     = a1 * inv + m1;
            out[o + 2 * plane] = a2 * inv + m2;
        }
        __syncthreads();   // stage boundary: protects ring-slot reuse
    }
}

// ---------------- launch ------------------------------------------------------
extern "C" void kernel_launch(void* const* d_in, const int* in_sizes, int n_in,
                              void* d_out, int out_size) {
    const float* noisy = (const float*)d_in[0];
    const float* deno  = (const float*)d_in[1];
    const float* pwts  = (const float*)d_in[2];
    float* out = (float*)d_out;

    cudaFuncSetAttribute(fold_kernel,
                         cudaFuncAttributeMaxDynamicSharedMemorySize,
                         SMEM_BYTES);

    dim3 mg(6, MEANS_CHUNKS);
    means_partial_kernel<<<mg, 512>>>(noisy);

    // PDL as in R13 (fire at drain; dependency deferred in-kernel to s==0).
    cudaLaunchAttribute attrs[1];
    attrs[0].id = cudaLaunchAttributeProgrammaticStreamSerialization;
    attrs[0].val.programmaticStreamSerializationAllowed = 1;

    cudaLaunchConfig_t cfg = {};
    cfg.gridDim  = dim3(NX, NSTRIPS, NT);   // 18 x 4 x 2 = 144 CTAs, one wave
    cfg.blockDim = dim3(TPB, 1, 1);
    cfg.dynamicSmemBytes = SMEM_BYTES;
    cfg.stream = 0;
    cfg.attrs = attrs;
    cfg.numAttrs = 1;

    cudaLaunchKernelEx(&cfg, fold_kernel, deno, pwts, out);
}